// round 9
// baseline (speedup 1.0000x reference)
#include <cuda_runtime.h>
#include <math.h>

#define NPTS   500000
#define MCLUS  50000

__device__ float g_agg[(size_t)MCLUS * 132];   // 131 used + 1 pad
__device__ float g_h[(size_t)MCLUS * 128];

// ---------------- helpers ----------------
__device__ __forceinline__ void red4(float* addr, float a, float b, float c, float d) {
    asm volatile("red.global.add.v4.f32 [%0], {%1,%2,%3,%4};"
                 :: "l"(addr), "f"(a), "f"(b), "f"(c), "f"(d) : "memory");
}
__device__ __forceinline__ void cpasync16(void* smem_dst, const void* gsrc) {
    unsigned saddr = (unsigned)__cvta_generic_to_shared(smem_dst);
    asm volatile("cp.async.ca.shared.global [%0], [%1], 16;" :: "r"(saddr), "l"(gsrc));
}
__device__ __forceinline__ void cp_commit() { asm volatile("cp.async.commit_group;"); }
__device__ __forceinline__ void cp_wait0()  { asm volatile("cp.async.wait_group 0;" ::: "memory"); }

__device__ __forceinline__ unsigned cvt_tf32(float f) {
    unsigned x;
    asm("cvt.rna.tf32.f32 %0, %1;" : "=r"(x) : "f"(f));
    return x;
}
__device__ __forceinline__ void mma_tf32(float* c, unsigned a0, unsigned a1,
                                         unsigned a2, unsigned a3,
                                         unsigned b0, unsigned b1) {
    asm volatile(
        "mma.sync.aligned.m16n8k8.row.col.f32.tf32.tf32.f32 "
        "{%0,%1,%2,%3}, {%4,%5,%6,%7}, {%8,%9}, {%0,%1,%2,%3};"
        : "+f"(c[0]), "+f"(c[1]), "+f"(c[2]), "+f"(c[3])
        : "r"(a0), "r"(a1), "r"(a2), "r"(a3), "r"(b0), "r"(b1));
}

#define SA  132   // A row stride (floats): bank=(4g+t) -> conflict-free LDS.32
#define SWR 40    // B half row stride (words): phase banks 8t+4g -> conflict-free LDS.128

// Full m32n64 tile body: 16 MMAs on shared B frags.
#define MMA_KF_BODY(sW0, sW1, LASTKF)                                          \
    {                                                                          \
        int kt = kf * 8 + t;                                                   \
        int kt4 = kt + 4;                                                      \
        unsigned a0 = cvt_tf32(A0[kt]);                                        \
        unsigned a1 = cvt_tf32(A1[kt]);                                        \
        unsigned a4 = cvt_tf32(A2[kt]);                                        \
        unsigned a5 = cvt_tf32(A3[kt]);                                        \
        unsigned a2, a3, a6, a7;                                               \
        if (LASTKF) { a2 = 0u; a3 = 0u; a6 = 0u; a7 = 0u; }                    \
        else {                                                                 \
            a2 = cvt_tf32(A0[kt4]); a3 = cvt_tf32(A1[kt4]);                    \
            a6 = cvt_tf32(A2[kt4]); a7 = cvt_tf32(A3[kt4]);                    \
        }                                                                      \
        uint4 blo  = *(const uint4*)(sW0 + kt * SWR + g * 4);                  \
        uint4 bhi  = *(const uint4*)(sW1 + kt * SWR + g * 4);                  \
        uint4 blo4 = *(const uint4*)(sW0 + kt4 * SWR + g * 4);                 \
        uint4 bhi4 = *(const uint4*)(sW1 + kt4 * SWR + g * 4);                 \
        mma_tf32(acc[0],  a0, a1, a2, a3, blo.x,  blo4.x);                     \
        mma_tf32(acc[1],  a0, a1, a2, a3, blo.y,  blo4.y);                     \
        mma_tf32(acc[2],  a0, a1, a2, a3, blo.z,  blo4.z);                     \
        mma_tf32(acc[3],  a0, a1, a2, a3, blo.w,  blo4.w);                     \
        mma_tf32(acc[4],  a0, a1, a2, a3, bhi.x,  bhi4.x);                     \
        mma_tf32(acc[5],  a0, a1, a2, a3, bhi.y,  bhi4.y);                     \
        mma_tf32(acc[6],  a0, a1, a2, a3, bhi.z,  bhi4.z);                     \
        mma_tf32(acc[7],  a0, a1, a2, a3, bhi.w,  bhi4.w);                     \
        mma_tf32(acc[8],  a4, a5, a6, a7, blo.x,  blo4.x);                     \
        mma_tf32(acc[9],  a4, a5, a6, a7, blo.y,  blo4.y);                     \
        mma_tf32(acc[10], a4, a5, a6, a7, blo.z,  blo4.z);                     \
        mma_tf32(acc[11], a4, a5, a6, a7, blo.w,  blo4.w);                     \
        mma_tf32(acc[12], a4, a5, a6, a7, bhi.x,  bhi4.x);                     \
        mma_tf32(acc[13], a4, a5, a6, a7, bhi.y,  bhi4.y);                     \
        mma_tf32(acc[14], a4, a5, a6, a7, bhi.z,  bhi4.z);                     \
        mma_tf32(acc[15], a4, a5, a6, a7, bhi.w,  bhi4.w);                     \
    }

// ---------------- kernel 0: zero agg ----------------
__global__ void zero_agg_kernel() {
    const size_t total4 = (size_t)MCLUS * 132 / 4;
    float4* p = (float4*)g_agg;
    float4 z = make_float4(0.f, 0.f, 0.f, 0.f);
    for (size_t i = blockIdx.x * blockDim.x + threadIdx.x; i < total4;
         i += (size_t)gridDim.x * blockDim.x)
        p[i] = z;
}

// ============ kernel 1: attention MLP (tf32 MMA, m32/warp) + scatter ============
// 128 threads = 4 warps, 128 rows/block.
__global__ void __launch_bounds__(128, 2) att_scatter_kernel(
    const float* __restrict__ feat, const float* __restrict__ pts,
    const float* __restrict__ ctr, const int* __restrict__ lab,
    const float* __restrict__ aW1, const float* __restrict__ ab1,
    const float* __restrict__ aW2, const float* __restrict__ ab2)
{
    extern __shared__ char dynRaw[];
    float*    sA  = (float*)dynRaw;                                // 128*SA
    unsigned* sW0 = (unsigned*)(dynRaw + 128 * SA * 4);            // 136*SWR
    unsigned* sW1 = sW0 + 136 * SWR;                               // 136*SWR
    float*    sB1 = (float*)(sW1 + 136 * SWR);                     // 64
    float*    sA2 = sB1 + 64;                                      // 64
    float*    sAtt = sA2 + 64;                                     // 128
    int*      sLab = (int*)(sAtt + 128);                           // 128
    float*    sb2p = (float*)(sLab + 128);

    const int tid = threadIdx.x;
    const int gbase = blockIdx.x * 128;
    const float4* f4 = (const float4*)feat;

    for (int idx = tid; idx < 128 * 32; idx += 128) {
        int row = idx >> 5, c4 = idx & 31;
        int gr = gbase + row; if (gr >= NPTS) gr = NPTS - 1;
        cpasync16(sA + row * SA + c4 * 4, f4 + (size_t)gr * 32 + c4);
    }
    cp_commit();

    for (int idx = tid; idx < 136 * 64; idx += 128) {
        int k = idx >> 6, n = idx & 63;
        float v = (k < 131) ? aW1[k * 64 + n] : 0.f;
        int nf = n >> 3, gg = n & 7;
        unsigned* dst = (nf < 4) ? sW0 : sW1;
        dst[k * SWR + gg * 4 + (nf & 3)] = cvt_tf32(v);
    }
    if (tid < 64) { sB1[tid] = ab1[tid]; sA2[tid] = aW2[tid]; }
    if (tid == 0) *sb2p = ab2[0];
    {
        int row = gbase + tid;
        int rc = (row < NPTS) ? row : (NPTS - 1);
        int l = lab[rc];
        sLab[tid] = l;
        float* Ar = sA + tid * SA;
        Ar[128] = ctr[l * 3 + 0] - pts[rc * 3 + 0];
        Ar[129] = ctr[l * 3 + 1] - pts[rc * 3 + 1];
        Ar[130] = ctr[l * 3 + 2] - pts[rc * 3 + 2];
        Ar[131] = 0.f;
    }
    cp_wait0();
    __syncthreads();

    const int w = tid >> 5;
    const int lane = tid & 31;
    const int g = lane >> 2;
    const int t = lane & 3;

    float acc[16][4];
#pragma unroll
    for (int i = 0; i < 16; i++) { acc[i][0] = 0.f; acc[i][1] = 0.f; acc[i][2] = 0.f; acc[i][3] = 0.f; }

    const float* A0 = sA + (w * 32 + g) * SA;
    const float* A1 = A0 + 8 * SA;
    const float* A2 = A0 + 16 * SA;
    const float* A3 = A0 + 24 * SA;

#pragma unroll 1
    for (int kf = 0; kf < 17; kf++) {
        MMA_KF_BODY(sW0, sW1, (kf == 16))
    }

    // epilogue: bias+relu -> dot aW2 -> reduce over t -> sigmoid -> sAtt
    {
        float s0 = 0.f, s1 = 0.f, s2 = 0.f, s3 = 0.f;
#pragma unroll
        for (int q = 0; q < 8; q++) {
            int base_c = (q < 4) ? q * 8 : 32 + (q - 4) * 8;
            int c0 = base_c + 2 * t, c1 = c0 + 1;
            float bb0 = sB1[c0], bb1 = sB1[c1];
            float w0 = sA2[c0], w1 = sA2[c1];
            s0 += fmaxf(acc[q][0] + bb0, 0.f) * w0 + fmaxf(acc[q][1] + bb1, 0.f) * w1;
            s1 += fmaxf(acc[q][2] + bb0, 0.f) * w0 + fmaxf(acc[q][3] + bb1, 0.f) * w1;
            s2 += fmaxf(acc[8 + q][0] + bb0, 0.f) * w0 + fmaxf(acc[8 + q][1] + bb1, 0.f) * w1;
            s3 += fmaxf(acc[8 + q][2] + bb0, 0.f) * w0 + fmaxf(acc[8 + q][3] + bb1, 0.f) * w1;
        }
        s0 += __shfl_xor_sync(0xffffffffu, s0, 1); s0 += __shfl_xor_sync(0xffffffffu, s0, 2);
        s1 += __shfl_xor_sync(0xffffffffu, s1, 1); s1 += __shfl_xor_sync(0xffffffffu, s1, 2);
        s2 += __shfl_xor_sync(0xffffffffu, s2, 1); s2 += __shfl_xor_sync(0xffffffffu, s2, 2);
        s3 += __shfl_xor_sync(0xffffffffu, s3, 1); s3 += __shfl_xor_sync(0xffffffffu, s3, 2);
        float b2v = *sb2p;
        if (t == 0) {
            sAtt[w * 32 + g]      = 1.f / (1.f + expf(-(s0 + b2v)));
            sAtt[w * 32 + g + 8]  = 1.f / (1.f + expf(-(s1 + b2v)));
            sAtt[w * 32 + g + 16] = 1.f / (1.f + expf(-(s2 + b2v)));
            sAtt[w * 32 + g + 24] = 1.f / (1.f + expf(-(s3 + b2v)));
        }
    }
    __syncthreads();

    // scatter: 1 thread per row, 33 red4 from the raw-fp32 A tile
    {
        int grow = gbase + tid;
        if (grow < NPTS) {
            float a = sAtt[tid];
            int l = sLab[tid];
            float* arow = g_agg + (size_t)l * 132;
            const float* Ar = sA + tid * SA;
#pragma unroll 1
            for (int c = 0; c < 33; c++) {
                float4 v = *(const float4*)(Ar + c * 4);
                red4(arow + c * 4, v.x * a, v.y * a, v.z * a, v.w * a);
            }
        }
    }
}

// ============ kernel 2: h = relu(agg @ oW1 + ob1)  (tf32 MMA m32) ============
// grid (391, 2): y = 64-col slice; 128 rows/block; K = 132 (136 B-rows)
__global__ void __launch_bounds__(128, 2) gemmB_kernel(
    const float* __restrict__ oW1, const float* __restrict__ ob1)
{
    extern __shared__ char dynRaw[];
    float*    sA  = (float*)dynRaw;                                // 128*SA
    unsigned* sW0 = (unsigned*)(dynRaw + 128 * SA * 4);            // 136*SWR
    unsigned* sW1 = sW0 + 136 * SWR;

    const int tid = threadIdx.x;
    const int slice = blockIdx.y;
    const int gbase = blockIdx.x * 128;
    const float4* a4 = (const float4*)g_agg;   // 33 f4/row == SA floats

    for (int idx = tid; idx < 128 * 33; idx += 128) {
        int row = idx / 33, c4 = idx - row * 33;
        int gr = gbase + row; if (gr >= MCLUS) gr = MCLUS - 1;
        cpasync16(sA + row * SA + c4 * 4, a4 + (size_t)gr * 33 + c4);
    }
    cp_commit();

    for (int idx = tid; idx < 136 * 64; idx += 128) {
        int k = idx >> 6, n = idx & 63;
        float v = (k < 131) ? oW1[k * 128 + slice * 64 + n] : 0.f;
        int nf = n >> 3, gg = n & 7;
        unsigned* dst = (nf < 4) ? sW0 : sW1;
        dst[k * SWR + gg * 4 + (nf & 3)] = cvt_tf32(v);
    }
    cp_wait0();
    __syncthreads();

    const int w = tid >> 5;
    const int lane = tid & 31;
    const int g = lane >> 2;
    const int t = lane & 3;

    float acc[16][4];
#pragma unroll
    for (int i = 0; i < 16; i++) { acc[i][0] = 0.f; acc[i][1] = 0.f; acc[i][2] = 0.f; acc[i][3] = 0.f; }

    const float* A0 = sA + (w * 32 + g) * SA;
    const float* A1 = A0 + 8 * SA;
    const float* A2 = A0 + 16 * SA;
    const float* A3 = A0 + 24 * SA;

#pragma unroll 1
    for (int kf = 0; kf < 17; kf++) {
        MMA_KF_BODY(sW0, sW1, (kf == 16))
    }

    int r0 = gbase + w * 32 + g;
#pragma unroll
    for (int q = 0; q < 8; q++) {
        int base_c = (q < 4) ? q * 8 : 32 + (q - 4) * 8;
        int c0 = slice * 64 + base_c + 2 * t;
        float bb0 = __ldg(ob1 + c0), bb1 = __ldg(ob1 + c0 + 1);
        if (r0 < MCLUS)
            *(float2*)(g_h + (size_t)r0 * 128 + c0) =
                make_float2(fmaxf(acc[q][0] + bb0, 0.f), fmaxf(acc[q][1] + bb1, 0.f));
        if (r0 + 8 < MCLUS)
            *(float2*)(g_h + (size_t)(r0 + 8) * 128 + c0) =
                make_float2(fmaxf(acc[q][2] + bb0, 0.f), fmaxf(acc[q][3] + bb1, 0.f));
        if (r0 + 16 < MCLUS)
            *(float2*)(g_h + (size_t)(r0 + 16) * 128 + c0) =
                make_float2(fmaxf(acc[8 + q][0] + bb0, 0.f), fmaxf(acc[8 + q][1] + bb1, 0.f));
        if (r0 + 24 < MCLUS)
            *(float2*)(g_h + (size_t)(r0 + 24) * 128 + c0) =
                make_float2(fmaxf(acc[8 + q][2] + bb0, 0.f), fmaxf(acc[8 + q][3] + bb1, 0.f));
    }
}

// ============ kernel 3: out = relu(h @ oW2 + ob2)  (tf32 MMA m32) ============
// grid (391, 4): y = 64-col slice; 128 rows/block; K = 128
__global__ void __launch_bounds__(128, 2) gemmC_kernel(
    const float* __restrict__ oW2, const float* __restrict__ ob2,
    float* __restrict__ out)
{
    extern __shared__ char dynRaw[];
    float*    sA  = (float*)dynRaw;                                // 128*SA
    unsigned* sW0 = (unsigned*)(dynRaw + 128 * SA * 4);            // 128*SWR
    unsigned* sW1 = sW0 + 128 * SWR;

    const int tid = threadIdx.x;
    const int slice = blockIdx.y;
    const int gbase = blockIdx.x * 128;
    const float4* h4 = (const float4*)g_h;   // 32 f4/row

    for (int idx = tid; idx < 128 * 32; idx += 128) {
        int row = idx >> 5, c4 = idx & 31;
        int gr = gbase + row; if (gr >= MCLUS) gr = MCLUS - 1;
        cpasync16(sA + row * SA + c4 * 4, h4 + (size_t)gr * 32 + c4);
    }
    cp_commit();

    for (int idx = tid; idx < 128 * 64; idx += 128) {
        int k = idx >> 6, n = idx & 63;
        int nf = n >> 3, gg = n & 7;
        unsigned* dst = (nf < 4) ? sW0 : sW1;
        dst[k * SWR + gg * 4 + (nf & 3)] = cvt_tf32(oW2[k * 256 + slice * 64 + n]);
    }
    cp_wait0();
    __syncthreads();

    const int w = tid >> 5;
    const int lane = tid & 31;
    const int g = lane >> 2;
    const int t = lane & 3;

    float acc[16][4];
#pragma unroll
    for (int i = 0; i < 16; i++) { acc[i][0] = 0.f; acc[i][1] = 0.f; acc[i][2] = 0.f; acc[i][3] = 0.f; }

    const float* A0 = sA + (w * 32 + g) * SA;
    const float* A1 = A0 + 8 * SA;
    const float* A2 = A0 + 16 * SA;
    const float* A3 = A0 + 24 * SA;

#pragma unroll 1
    for (int kf = 0; kf < 16; kf++) {
        MMA_KF_BODY(sW0, sW1, false)
    }

    int r0 = gbase + w * 32 + g;
#pragma unroll
    for (int q = 0; q < 8; q++) {
        int base_c = (q < 4) ? q * 8 : 32 + (q - 4) * 8;
        int c0 = slice * 64 + base_c + 2 * t;
        float bb0 = __ldg(ob2 + c0), bb1 = __ldg(ob2 + c0 + 1);
        if (r0 < MCLUS)
            *(float2*)(out + (size_t)r0 * 256 + c0) =
                make_float2(fmaxf(acc[q][0] + bb0, 0.f), fmaxf(acc[q][1] + bb1, 0.f));
        if (r0 + 8 < MCLUS)
            *(float2*)(out + (size_t)(r0 + 8) * 256 + c0) =
                make_float2(fmaxf(acc[q][2] + bb0, 0.f), fmaxf(acc[q][3] + bb1, 0.f));
        if (r0 + 16 < MCLUS)
            *(float2*)(out + (size_t)(r0 + 16) * 256 + c0) =
                make_float2(fmaxf(acc[8 + q][0] + bb0, 0.f), fmaxf(acc[8 + q][1] + bb1, 0.f));
        if (r0 + 24 < MCLUS)
            *(float2*)(out + (size_t)(r0 + 24) * 256 + c0) =
                make_float2(fmaxf(acc[8 + q][2] + bb0, 0.f), fmaxf(acc[8 + q][3] + bb1, 0.f));
    }
}

extern "C" void kernel_launch(void* const* d_in, const int* in_sizes, int n_in,
                              void* d_out, int out_size) {
    const float* feat = (const float*)d_in[0];
    const float* pts  = (const float*)d_in[1];
    const float* ctr  = (const float*)d_in[2];
    const int*   lab  = (const int*)d_in[3];
    const float* aW1  = (const float*)d_in[4];
    const float* ab1  = (const float*)d_in[5];
    const float* aW2  = (const float*)d_in[6];
    const float* ab2  = (const float*)d_in[7];
    const float* oW1  = (const float*)d_in[8];
    const float* ob1  = (const float*)d_in[9];
    const float* oW2  = (const float*)d_in[10];
    const float* ob2  = (const float*)d_in[11];
    float* out = (float*)d_out;

    const int attSmem = 128 * SA * 4 + 2 * 136 * SWR * 4 + (64 + 64 + 128) * 4 + 128 * 4 + 16;
    const int bSmem   = 128 * SA * 4 + 2 * 136 * SWR * 4;
    const int cSmem   = 128 * SA * 4 + 2 * 128 * SWR * 4;

    static int inited = 0;
    if (!inited) {
        cudaFuncSetAttribute(att_scatter_kernel, cudaFuncAttributeMaxDynamicSharedMemorySize, attSmem);
        cudaFuncSetAttribute(gemmB_kernel, cudaFuncAttributeMaxDynamicSharedMemorySize, bSmem);
        cudaFuncSetAttribute(gemmC_kernel, cudaFuncAttributeMaxDynamicSharedMemorySize, cSmem);
        inited = 1;
    }

    zero_agg_kernel<<<2048, 256>>>();
    att_scatter_kernel<<<(NPTS + 127) / 128, 128, attSmem>>>(feat, pts, ctr, lab,
                                                             aW1, ab1, aW2, ab2);
    gemmB_kernel<<<dim3((MCLUS + 127) / 128, 2), 128, bSmem>>>(oW1, ob1);
    gemmC_kernel<<<dim3((MCLUS + 127) / 128, 4), 128, cSmem>>>(oW2, ob2, out);
}

// round 10
// speedup vs baseline: 1.2287x; 1.2287x over previous
#include <cuda_runtime.h>
#include <math.h>

#define NPTS   500000
#define MCLUS  50000

__device__ float g_agg[(size_t)MCLUS * 132];   // 131 used + 1 pad
__device__ float g_h[(size_t)MCLUS * 128];

// ---------------- helpers ----------------
__device__ __forceinline__ void red4(float* addr, float a, float b, float c, float d) {
    asm volatile("red.global.add.v4.f32 [%0], {%1,%2,%3,%4};"
                 :: "l"(addr), "f"(a), "f"(b), "f"(c), "f"(d) : "memory");
}
__device__ __forceinline__ void cpasync16(void* smem_dst, const void* gsrc) {
    unsigned saddr = (unsigned)__cvta_generic_to_shared(smem_dst);
    asm volatile("cp.async.ca.shared.global [%0], [%1], 16;" :: "r"(saddr), "l"(gsrc));
}
__device__ __forceinline__ void cp_commit() { asm volatile("cp.async.commit_group;"); }
__device__ __forceinline__ void cp_wait0()  { asm volatile("cp.async.wait_group 0;" ::: "memory"); }

__device__ __forceinline__ unsigned cvt_tf32(float f) {
    unsigned x;
    asm("cvt.rna.tf32.f32 %0, %1;" : "=r"(x) : "f"(f));
    return x;
}
__device__ __forceinline__ void mma_tf32(float* c, unsigned a0, unsigned a1,
                                         unsigned a2, unsigned a3,
                                         unsigned b0, unsigned b1) {
    asm volatile(
        "mma.sync.aligned.m16n8k8.row.col.f32.tf32.tf32.f32 "
        "{%0,%1,%2,%3}, {%4,%5,%6,%7}, {%8,%9}, {%0,%1,%2,%3};"
        : "+f"(c[0]), "+f"(c[1]), "+f"(c[2]), "+f"(c[3])
        : "r"(a0), "r"(a1), "r"(a2), "r"(a3), "r"(b0), "r"(b1));
}

#define SA  136   // A row stride (floats): bank=(8g+t) -> conflict-free
#define SWR 40    // B half row stride (words): LDS.128 phase-conflict-free

// m16n64 per-warp kf body: 8 MMAs, 4 LDS.128 B, 4 LDS.32 A.
// acc[q] covers cols q*8 + {2t, 2t+1}.
#define MMA_KF16(sW0_, sW1_)                                                  \
    {                                                                         \
        int kt = kf * 8 + t;                                                  \
        int kt4 = kt + 4;                                                     \
        unsigned a0 = cvt_tf32(Ar0[kt]);                                      \
        unsigned a1 = cvt_tf32(Ar1[kt]);                                      \
        unsigned a2 = cvt_tf32(Ar0[kt4]);                                     \
        unsigned a3 = cvt_tf32(Ar1[kt4]);                                     \
        uint4 blo  = *(const uint4*)(sW0_ + kt * SWR + g * 4);                \
        uint4 bhi  = *(const uint4*)(sW1_ + kt * SWR + g * 4);                \
        uint4 blo4 = *(const uint4*)(sW0_ + kt4 * SWR + g * 4);               \
        uint4 bhi4 = *(const uint4*)(sW1_ + kt4 * SWR + g * 4);               \
        mma_tf32(acc[0], a0, a1, a2, a3, blo.x, blo4.x);                      \
        mma_tf32(acc[1], a0, a1, a2, a3, blo.y, blo4.y);                      \
        mma_tf32(acc[2], a0, a1, a2, a3, blo.z, blo4.z);                      \
        mma_tf32(acc[3], a0, a1, a2, a3, blo.w, blo4.w);                      \
        mma_tf32(acc[4], a0, a1, a2, a3, bhi.x, bhi4.x);                      \
        mma_tf32(acc[5], a0, a1, a2, a3, bhi.y, bhi4.y);                      \
        mma_tf32(acc[6], a0, a1, a2, a3, bhi.z, bhi4.z);                      \
        mma_tf32(acc[7], a0, a1, a2, a3, bhi.w, bhi4.w);                      \
    }

// ---------------- kernel 0: zero agg ----------------
__global__ void zero_agg_kernel() {
    const size_t total4 = (size_t)MCLUS * 132 / 4;
    float4* p = (float4*)g_agg;
    float4 z = make_float4(0.f, 0.f, 0.f, 0.f);
    for (size_t i = blockIdx.x * blockDim.x + threadIdx.x; i < total4;
         i += (size_t)gridDim.x * blockDim.x)
        p[i] = z;
}

// ============ kernel 1: attention MLP (tf32 MMA) + scatter ============
// 256 threads = 8 warps, 128 rows/block, warp w owns rows w*16..w*16+15.
__global__ void __launch_bounds__(256, 2) att_scatter_kernel(
    const float* __restrict__ feat, const float* __restrict__ pts,
    const float* __restrict__ ctr, const int* __restrict__ lab,
    const float* __restrict__ aW1, const float* __restrict__ ab1,
    const float* __restrict__ aW2, const float* __restrict__ ab2)
{
    extern __shared__ char dynRaw[];
    float*    sA  = (float*)dynRaw;                                // 128*SA
    unsigned* sW0 = (unsigned*)(dynRaw + 128 * SA * 4);            // 136*SWR
    unsigned* sW1 = sW0 + 136 * SWR;                               // 136*SWR
    float*    sB1 = (float*)(sW1 + 136 * SWR);                     // 64
    float*    sA2 = sB1 + 64;                                      // 64
    float*    sAtt = sA2 + 64;                                     // 128
    int*      sLab = (int*)(sAtt + 128);                           // 128
    float*    sb2p = (float*)(sLab + 128);

    const int tid = threadIdx.x;
    const int gbase = blockIdx.x * 128;
    const float4* f4 = (const float4*)feat;

    for (int idx = tid; idx < 128 * 32; idx += 256) {
        int row = idx >> 5, c4 = idx & 31;
        int gr = gbase + row; if (gr >= NPTS) gr = NPTS - 1;
        cpasync16(sA + row * SA + c4 * 4, f4 + (size_t)gr * 32 + c4);
    }
    cp_commit();

    for (int idx = tid; idx < 136 * 64; idx += 256) {
        int k = idx >> 6, n = idx & 63;
        float v = (k < 131) ? aW1[k * 64 + n] : 0.f;
        int nf = n >> 3, gg = n & 7;
        unsigned* dst = (nf < 4) ? sW0 : sW1;
        dst[k * SWR + gg * 4 + (nf & 3)] = cvt_tf32(v);
    }
    if (tid < 64) { sB1[tid] = ab1[tid]; sA2[tid] = aW2[tid]; }
    if (tid == 0) *sb2p = ab2[0];
    if (tid < 128) {
        int row = gbase + tid;
        int rc = (row < NPTS) ? row : (NPTS - 1);
        int l = lab[rc];
        sLab[tid] = l;
        float* Ar = sA + tid * SA;
        Ar[128] = ctr[l * 3 + 0] - pts[rc * 3 + 0];
        Ar[129] = ctr[l * 3 + 1] - pts[rc * 3 + 1];
        Ar[130] = ctr[l * 3 + 2] - pts[rc * 3 + 2];
        Ar[131] = 0.f; Ar[132] = 0.f; Ar[133] = 0.f; Ar[134] = 0.f; Ar[135] = 0.f;
    }
    cp_wait0();
    __syncthreads();

    const int w = tid >> 5;
    const int lane = tid & 31;
    const int g = lane >> 2;
    const int t = lane & 3;

    float acc[8][4];
#pragma unroll
    for (int i = 0; i < 8; i++) { acc[i][0] = 0.f; acc[i][1] = 0.f; acc[i][2] = 0.f; acc[i][3] = 0.f; }

    const float* Ar0 = sA + (w * 16 + g) * SA;
    const float* Ar1 = Ar0 + 8 * SA;

#pragma unroll 1
    for (int kf = 0; kf < 17; kf++) {
        MMA_KF16(sW0, sW1)
    }

    // epilogue: bias+relu -> dot aW2 -> reduce over t -> sigmoid -> sAtt
    {
        float s0 = 0.f, s1 = 0.f;
#pragma unroll
        for (int q = 0; q < 8; q++) {
            int c0 = q * 8 + 2 * t, c1 = c0 + 1;
            float bb0 = sB1[c0], bb1 = sB1[c1];
            float w0 = sA2[c0], w1 = sA2[c1];
            s0 += fmaxf(acc[q][0] + bb0, 0.f) * w0 + fmaxf(acc[q][1] + bb1, 0.f) * w1;
            s1 += fmaxf(acc[q][2] + bb0, 0.f) * w0 + fmaxf(acc[q][3] + bb1, 0.f) * w1;
        }
        s0 += __shfl_xor_sync(0xffffffffu, s0, 1);
        s0 += __shfl_xor_sync(0xffffffffu, s0, 2);
        s1 += __shfl_xor_sync(0xffffffffu, s1, 1);
        s1 += __shfl_xor_sync(0xffffffffu, s1, 2);
        float b2v = *sb2p;
        if (t == 0) {
            sAtt[w * 16 + g]     = 1.f / (1.f + expf(-(s0 + b2v)));
            sAtt[w * 16 + g + 8] = 1.f / (1.f + expf(-(s1 + b2v)));
        }
    }
    __syncthreads();

    // scatter: 2 threads per row, red4 from the raw-fp32 A tile
    {
        int row = tid >> 1, half = tid & 1;
        int grow = gbase + row;
        if (grow < NPTS) {
            float a = sAtt[row];
            int l = sLab[row];
            float* arow = g_agg + (size_t)l * 132;
            const float* Ar = sA + row * SA;
            int c_lo = half ? 17 : 0;
            int c_hi = half ? 33 : 17;
#pragma unroll 1
            for (int c = c_lo; c < c_hi; c++) {
                float4 v = *(const float4*)(Ar + c * 4);
                red4(arow + c * 4, v.x * a, v.y * a, v.z * a, v.w * a);
            }
        }
    }
}

// ============ kernel 2: h = relu(agg @ oW1 + ob1)  (tf32 MMA) ============
// grid (391, 2): y = 64-col slice; 128 rows/block; K = 132 (136 padded)
__global__ void __launch_bounds__(256, 2) gemmB_kernel(
    const float* __restrict__ oW1, const float* __restrict__ ob1)
{
    extern __shared__ char dynRaw[];
    float*    sA  = (float*)dynRaw;                                // 128*SA
    unsigned* sW0 = (unsigned*)(dynRaw + 128 * SA * 4);            // 136*SWR
    unsigned* sW1 = sW0 + 136 * SWR;

    const int tid = threadIdx.x;
    const int slice = blockIdx.y;
    const int gbase = blockIdx.x * 128;
    const float4* a4 = (const float4*)g_agg;   // 33 f4/row

    for (int idx = tid; idx < 128 * 33; idx += 256) {
        int row = idx / 33, c4 = idx - row * 33;
        int gr = gbase + row; if (gr >= MCLUS) gr = MCLUS - 1;
        cpasync16(sA + row * SA + c4 * 4, a4 + (size_t)gr * 33 + c4);
    }
    cp_commit();

    for (int idx = tid; idx < 136 * 64; idx += 256) {
        int k = idx >> 6, n = idx & 63;
        float v = (k < 131) ? oW1[k * 128 + slice * 64 + n] : 0.f;
        int nf = n >> 3, gg = n & 7;
        unsigned* dst = (nf < 4) ? sW0 : sW1;
        dst[k * SWR + gg * 4 + (nf & 3)] = cvt_tf32(v);
    }
    if (tid < 128) {   // zero A cols 132..135 (avoid garbage * 0-weight NaN)
        float* Ar = sA + tid * SA;
        Ar[132] = 0.f; Ar[133] = 0.f; Ar[134] = 0.f; Ar[135] = 0.f;
    }
    cp_wait0();
    __syncthreads();

    const int w = tid >> 5;
    const int lane = tid & 31;
    const int g = lane >> 2;
    const int t = lane & 3;

    float acc[8][4];
#pragma unroll
    for (int i = 0; i < 8; i++) { acc[i][0] = 0.f; acc[i][1] = 0.f; acc[i][2] = 0.f; acc[i][3] = 0.f; }

    const float* Ar0 = sA + (w * 16 + g) * SA;
    const float* Ar1 = Ar0 + 8 * SA;

#pragma unroll 1
    for (int kf = 0; kf < 17; kf++) {
        MMA_KF16(sW0, sW1)
    }

    int r0 = gbase + w * 16 + g;
    int r1 = r0 + 8;
#pragma unroll
    for (int q = 0; q < 8; q++) {
        int c0 = slice * 64 + q * 8 + 2 * t;
        float bb0 = __ldg(ob1 + c0), bb1 = __ldg(ob1 + c0 + 1);
        if (r0 < MCLUS)
            *(float2*)(g_h + (size_t)r0 * 128 + c0) =
                make_float2(fmaxf(acc[q][0] + bb0, 0.f), fmaxf(acc[q][1] + bb1, 0.f));
        if (r1 < MCLUS)
            *(float2*)(g_h + (size_t)r1 * 128 + c0) =
                make_float2(fmaxf(acc[q][2] + bb0, 0.f), fmaxf(acc[q][3] + bb1, 0.f));
    }
}

// ============ kernel 3: out = relu(h @ oW2 + ob2)  (tf32 MMA) ============
// grid (391, 4): y = 64-col slice; 128 rows/block; K = 128
__global__ void __launch_bounds__(256, 2) gemmC_kernel(
    const float* __restrict__ oW2, const float* __restrict__ ob2,
    float* __restrict__ out)
{
    extern __shared__ char dynRaw[];
    float*    sA  = (float*)dynRaw;                                // 128*SA
    unsigned* sW0 = (unsigned*)(dynRaw + 128 * SA * 4);            // 128*SWR
    unsigned* sW1 = sW0 + 128 * SWR;

    const int tid = threadIdx.x;
    const int slice = blockIdx.y;
    const int gbase = blockIdx.x * 128;
    const float4* h4 = (const float4*)g_h;   // 32 f4/row

    for (int idx = tid; idx < 128 * 32; idx += 256) {
        int row = idx >> 5, c4 = idx & 31;
        int gr = gbase + row; if (gr >= MCLUS) gr = MCLUS - 1;
        cpasync16(sA + row * SA + c4 * 4, h4 + (size_t)gr * 32 + c4);
    }
    cp_commit();

    for (int idx = tid; idx < 128 * 64; idx += 256) {
        int k = idx >> 6, n = idx & 63;
        int nf = n >> 3, gg = n & 7;
        unsigned* dst = (nf < 4) ? sW0 : sW1;
        dst[k * SWR + gg * 4 + (nf & 3)] = cvt_tf32(oW2[k * 256 + slice * 64 + n]);
    }
    cp_wait0();
    __syncthreads();

    const int w = tid >> 5;
    const int lane = tid & 31;
    const int g = lane >> 2;
    const int t = lane & 3;

    float acc[8][4];
#pragma unroll
    for (int i = 0; i < 8; i++) { acc[i][0] = 0.f; acc[i][1] = 0.f; acc[i][2] = 0.f; acc[i][3] = 0.f; }

    const float* Ar0 = sA + (w * 16 + g) * SA;
    const float* Ar1 = Ar0 + 8 * SA;

#pragma unroll 1
    for (int kf = 0; kf < 16; kf++) {
        MMA_KF16(sW0, sW1)
    }

    int r0 = gbase + w * 16 + g;
    int r1 = r0 + 8;
#pragma unroll
    for (int q = 0; q < 8; q++) {
        int c0 = slice * 64 + q * 8 + 2 * t;
        float bb0 = __ldg(ob2 + c0), bb1 = __ldg(ob2 + c0 + 1);
        if (r0 < MCLUS)
            *(float2*)(out + (size_t)r0 * 256 + c0) =
                make_float2(fmaxf(acc[q][0] + bb0, 0.f), fmaxf(acc[q][1] + bb1, 0.f));
        if (r1 < MCLUS)
            *(float2*)(out + (size_t)r1 * 256 + c0) =
                make_float2(fmaxf(acc[q][2] + bb0, 0.f), fmaxf(acc[q][3] + bb1, 0.f));
    }
}

extern "C" void kernel_launch(void* const* d_in, const int* in_sizes, int n_in,
                              void* d_out, int out_size) {
    const float* feat = (const float*)d_in[0];
    const float* pts  = (const float*)d_in[1];
    const float* ctr  = (const float*)d_in[2];
    const int*   lab  = (const int*)d_in[3];
    const float* aW1  = (const float*)d_in[4];
    const float* ab1  = (const float*)d_in[5];
    const float* aW2  = (const float*)d_in[6];
    const float* ab2  = (const float*)d_in[7];
    const float* oW1  = (const float*)d_in[8];
    const float* ob1  = (const float*)d_in[9];
    const float* oW2  = (const float*)d_in[10];
    const float* ob2  = (const float*)d_in[11];
    float* out = (float*)d_out;

    const int attSmem = 128 * SA * 4 + 2 * 136 * SWR * 4 + (64 + 64 + 128) * 4 + 128 * 4 + 16;
    const int bSmem   = 128 * SA * 4 + 2 * 136 * SWR * 4;
    const int cSmem   = 128 * SA * 4 + 2 * 128 * SWR * 4;

    static int inited = 0;
    if (!inited) {
        cudaFuncSetAttribute(att_scatter_kernel, cudaFuncAttributeMaxDynamicSharedMemorySize, attSmem);
        cudaFuncSetAttribute(gemmB_kernel, cudaFuncAttributeMaxDynamicSharedMemorySize, bSmem);
        cudaFuncSetAttribute(gemmC_kernel, cudaFuncAttributeMaxDynamicSharedMemorySize, cSmem);
        inited = 1;
    }

    zero_agg_kernel<<<2048, 256>>>();
    att_scatter_kernel<<<(NPTS + 127) / 128, 256, attSmem>>>(feat, pts, ctr, lab,
                                                             aW1, ab1, aW2, ab2);
    gemmB_kernel<<<dim3((MCLUS + 127) / 128, 2), 256, bSmem>>>(oW1, ob1);
    gemmC_kernel<<<dim3((MCLUS + 127) / 128, 4), 256, cSmem>>>(oW2, ob2, out);
}

// round 11
// speedup vs baseline: 1.5859x; 1.2907x over previous
#include <cuda_runtime.h>
#include <math.h>

#define NPTS   500000
#define MCLUS  50000
#define NTILE_ATT ((NPTS + 127) / 128)    // 3907
#define NTILE_M   ((MCLUS + 127) / 128)   // 391

__device__ float g_agg[(size_t)MCLUS * 132];   // 131 used + 1 pad
__device__ float g_h[(size_t)MCLUS * 128];

// ---------------- helpers ----------------
__device__ __forceinline__ void red4(float* addr, float a, float b, float c, float d) {
    asm volatile("red.global.add.v4.f32 [%0], {%1,%2,%3,%4};"
                 :: "l"(addr), "f"(a), "f"(b), "f"(c), "f"(d) : "memory");
}
__device__ __forceinline__ void cpasync16(void* smem_dst, const void* gsrc) {
    unsigned saddr = (unsigned)__cvta_generic_to_shared(smem_dst);
    asm volatile("cp.async.cg.shared.global [%0], [%1], 16;" :: "r"(saddr), "l"(gsrc));
}
__device__ __forceinline__ void cp_commit() { asm volatile("cp.async.commit_group;"); }
__device__ __forceinline__ void cp_wait0()  { asm volatile("cp.async.wait_group 0;" ::: "memory"); }

__device__ __forceinline__ unsigned cvt_tf32(float f) {
    unsigned x;
    asm("cvt.rna.tf32.f32 %0, %1;" : "=r"(x) : "f"(f));
    return x;
}
__device__ __forceinline__ void mma_tf32(float* c, unsigned a0, unsigned a1,
                                         unsigned a2, unsigned a3,
                                         unsigned b0, unsigned b1) {
    asm volatile(
        "mma.sync.aligned.m16n8k8.row.col.f32.tf32.tf32.f32 "
        "{%0,%1,%2,%3}, {%4,%5,%6,%7}, {%8,%9}, {%0,%1,%2,%3};"
        : "+f"(c[0]), "+f"(c[1]), "+f"(c[2]), "+f"(c[3])
        : "r"(a0), "r"(a1), "r"(a2), "r"(a3), "r"(b0), "r"(b1));
}

#define SA 136   // A-tile row stride (floats): conflict-free
#define SB 72    // B-tile row stride (tf32 words): conflict-free

// ---------------- kernel 0: zero agg ----------------
__global__ void zero_agg_kernel() {
    const size_t total4 = (size_t)MCLUS * 132 / 4;
    float4* p = (float4*)g_agg;
    float4 z = make_float4(0.f, 0.f, 0.f, 0.f);
    for (size_t i = blockIdx.x * blockDim.x + threadIdx.x; i < total4;
         i += (size_t)gridDim.x * blockDim.x)
        p[i] = z;
}

// ============ kernel 1: attention MLP (tf32 MMA) + scatter, persistent ============
__global__ void __launch_bounds__(256, 2) att_scatter_kernel(
    const float* __restrict__ feat, const float* __restrict__ pts,
    const float* __restrict__ ctr, const int* __restrict__ lab,
    const float* __restrict__ aW1, const float* __restrict__ ab1,
    const float* __restrict__ aW2, const float* __restrict__ ab2)
{
    extern __shared__ char dynRaw[];
    float*    sA  = (float*)dynRaw;                       // 128*SA floats
    unsigned* sWb = (unsigned*)(dynRaw + 128 * SA * 4);   // 136*SB tf32 bits
    float*    sB1 = (float*)(dynRaw + 128 * SA * 4 + 136 * SB * 4);  // 64
    float*    sA2 = sB1 + 64;          // 64
    float*    sAtt = sA2 + 64;         // 128
    int*      sLab = (int*)(sAtt + 128);  // 128
    float*    sb2p = (float*)(sLab + 128);

    const int tid = threadIdx.x;
    const float4* f4 = (const float4*)feat;

    // stage weights (tf32-rounded) + biases ONCE
    for (int idx = tid; idx < 136 * 64; idx += 256) {
        int k = idx >> 6, n = idx & 63;
        float v = (k < 131) ? aW1[k * 64 + n] : 0.f;
        sWb[k * SB + n] = cvt_tf32(v);
    }
    if (tid < 64) { sB1[tid] = ab1[tid]; sA2[tid] = aW2[tid]; }
    if (tid == 0) *sb2p = ab2[0];

    const int w = tid >> 5;
    const int lane = tid & 31;
    const int g = lane >> 2;
    const int t = lane & 3;

    for (int tile = blockIdx.x; tile < NTILE_ATT; tile += gridDim.x) {
        const int gbase = tile * 128;

        // stage A tile (cp.async.cg) + rel coords + labels
        for (int idx = tid; idx < 128 * 32; idx += 256) {
            int row = idx >> 5, c4 = idx & 31;
            int gr = gbase + row; if (gr >= NPTS) gr = NPTS - 1;
            cpasync16(sA + row * SA + c4 * 4, f4 + (size_t)gr * 32 + c4);
        }
        cp_commit();
        if (tid < 128) {
            int row = gbase + tid;
            int rc = (row < NPTS) ? row : (NPTS - 1);
            int l = lab[rc];
            sLab[tid] = l;
            float* Ar = sA + tid * SA;
            Ar[128] = ctr[l * 3 + 0] - pts[rc * 3 + 0];
            Ar[129] = ctr[l * 3 + 1] - pts[rc * 3 + 1];
            Ar[130] = ctr[l * 3 + 2] - pts[rc * 3 + 2];
            Ar[131] = 0.f; Ar[132] = 0.f; Ar[133] = 0.f; Ar[134] = 0.f; Ar[135] = 0.f;
        }
        cp_wait0();
        __syncthreads();

        float acc[8][4];
#pragma unroll
        for (int nf = 0; nf < 8; nf++) {
            acc[nf][0] = 0.f; acc[nf][1] = 0.f; acc[nf][2] = 0.f; acc[nf][3] = 0.f;
        }

        const float* Ar0 = sA + (w * 16 + g) * SA;
        const float* Ar1 = Ar0 + 8 * SA;

#pragma unroll 1
        for (int kf = 0; kf < 17; kf++) {
            int k0 = kf * 8;
            unsigned a0 = cvt_tf32(Ar0[k0 + t]);
            unsigned a1 = cvt_tf32(Ar1[k0 + t]);
            unsigned a2 = cvt_tf32(Ar0[k0 + t + 4]);
            unsigned a3 = cvt_tf32(Ar1[k0 + t + 4]);
            const unsigned* B0 = sWb + (k0 + t) * SB + g;
            const unsigned* B1 = sWb + (k0 + t + 4) * SB + g;
#pragma unroll
            for (int nf = 0; nf < 8; nf++) {
                mma_tf32(acc[nf], a0, a1, a2, a3, B0[nf * 8], B1[nf * 8]);
            }
        }

        // epilogue: bias+relu -> dot aW2 -> reduce over t -> sigmoid -> sAtt
        {
            float s0 = 0.f, s1 = 0.f;
#pragma unroll
            for (int nf = 0; nf < 8; nf++) {
                int c0 = nf * 8 + 2 * t, c1 = c0 + 1;
                float bb0 = sB1[c0], bb1 = sB1[c1];
                float w0 = sA2[c0], w1 = sA2[c1];
                s0 += fmaxf(acc[nf][0] + bb0, 0.f) * w0 + fmaxf(acc[nf][1] + bb1, 0.f) * w1;
                s1 += fmaxf(acc[nf][2] + bb0, 0.f) * w0 + fmaxf(acc[nf][3] + bb1, 0.f) * w1;
            }
            s0 += __shfl_xor_sync(0xffffffffu, s0, 1);
            s0 += __shfl_xor_sync(0xffffffffu, s0, 2);
            s1 += __shfl_xor_sync(0xffffffffu, s1, 1);
            s1 += __shfl_xor_sync(0xffffffffu, s1, 2);
            float b2v = *sb2p;
            if (t == 0) {
                sAtt[w * 16 + g]     = 1.f / (1.f + expf(-(s0 + b2v)));
                sAtt[w * 16 + g + 8] = 1.f / (1.f + expf(-(s1 + b2v)));
            }
        }
        __syncthreads();

        // scatter: 2 threads per row, red4 from the raw-fp32 A tile
        {
            int row = tid >> 1, half = tid & 1;
            int grow = gbase + row;
            if (grow < NPTS) {
                float a = sAtt[row];
                int l = sLab[row];
                float* arow = g_agg + (size_t)l * 132;
                const float* Ar = sA + row * SA;
                int c_lo = half ? 17 : 0;
                int c_hi = half ? 33 : 17;
#pragma unroll 1
                for (int c = c_lo; c < c_hi; c++) {
                    float4 v = *(const float4*)(Ar + c * 4);
                    red4(arow + c * 4, v.x * a, v.y * a, v.z * a, v.w * a);
                }
            }
        }
        __syncthreads();   // sA reads done before next tile restage
    }
}

// ============ kernel 2: h = relu(agg @ oW1 + ob1)  (tf32 MMA, persistent) ============
// grid (148, 2): y = 64-col slice
__global__ void __launch_bounds__(256, 2) gemmB_kernel(
    const float* __restrict__ oW1, const float* __restrict__ ob1)
{
    extern __shared__ char dynRaw[];
    float*    sA  = (float*)dynRaw;                       // 128*SA
    unsigned* sWb = (unsigned*)(dynRaw + 128 * SA * 4);   // 136*SB

    const int tid = threadIdx.x;
    const int slice = blockIdx.y;
    const float4* a4 = (const float4*)g_agg;   // 33 f4/row

    for (int idx = tid; idx < 136 * 64; idx += 256) {
        int k = idx >> 6, n = idx & 63;
        float v = (k < 131) ? oW1[k * 128 + slice * 64 + n] : 0.f;
        sWb[k * SB + n] = cvt_tf32(v);
    }

    const int w = tid >> 5;
    const int lane = tid & 31;
    const int g = lane >> 2;
    const int t = lane & 3;

    for (int tile = blockIdx.x; tile < NTILE_M; tile += gridDim.x) {
        const int gbase = tile * 128;

        for (int idx = tid; idx < 128 * 33; idx += 256) {
            int row = idx / 33, c4 = idx - row * 33;
            int gr = gbase + row; if (gr >= MCLUS) gr = MCLUS - 1;
            cpasync16(sA + row * SA + c4 * 4, a4 + (size_t)gr * 33 + c4);
        }
        cp_commit();
        if (tid < 128) {   // zero A cols 132..135
            float* Ar = sA + tid * SA;
            Ar[132] = 0.f; Ar[133] = 0.f; Ar[134] = 0.f; Ar[135] = 0.f;
        }
        cp_wait0();
        __syncthreads();

        float acc[8][4];
#pragma unroll
        for (int nf = 0; nf < 8; nf++) {
            acc[nf][0] = 0.f; acc[nf][1] = 0.f; acc[nf][2] = 0.f; acc[nf][3] = 0.f;
        }

        const float* Ar0 = sA + (w * 16 + g) * SA;
        const float* Ar1 = Ar0 + 8 * SA;

#pragma unroll 1
        for (int kf = 0; kf < 17; kf++) {
            int k0 = kf * 8;
            unsigned a0 = cvt_tf32(Ar0[k0 + t]);
            unsigned a1 = cvt_tf32(Ar1[k0 + t]);
            unsigned a2 = cvt_tf32(Ar0[k0 + t + 4]);
            unsigned a3 = cvt_tf32(Ar1[k0 + t + 4]);
            const unsigned* B0 = sWb + (k0 + t) * SB + g;
            const unsigned* B1 = sWb + (k0 + t + 4) * SB + g;
#pragma unroll
            for (int nf = 0; nf < 8; nf++) {
                mma_tf32(acc[nf], a0, a1, a2, a3, B0[nf * 8], B1[nf * 8]);
            }
        }

        int r0 = gbase + w * 16 + g;
        int r1 = r0 + 8;
#pragma unroll
        for (int nf = 0; nf < 8; nf++) {
            int c0 = slice * 64 + nf * 8 + 2 * t;
            float bb0 = __ldg(ob1 + c0), bb1 = __ldg(ob1 + c0 + 1);
            if (r0 < MCLUS)
                *(float2*)(g_h + (size_t)r0 * 128 + c0) =
                    make_float2(fmaxf(acc[nf][0] + bb0, 0.f), fmaxf(acc[nf][1] + bb1, 0.f));
            if (r1 < MCLUS)
                *(float2*)(g_h + (size_t)r1 * 128 + c0) =
                    make_float2(fmaxf(acc[nf][2] + bb0, 0.f), fmaxf(acc[nf][3] + bb1, 0.f));
        }
        __syncthreads();   // done reading sA before restage
    }
}

// ============ kernel 3: out = relu(h @ oW2 + ob2)  (tf32 MMA, persistent) ============
// grid (74, 4): y = 64-col slice
__global__ void __launch_bounds__(256, 2) gemmC_kernel(
    const float* __restrict__ oW2, const float* __restrict__ ob2,
    float* __restrict__ out)
{
    extern __shared__ char dynRaw[];
    float*    sA  = (float*)dynRaw;                       // 128*SA
    unsigned* sWb = (unsigned*)(dynRaw + 128 * SA * 4);   // 128*SB

    const int tid = threadIdx.x;
    const int slice = blockIdx.y;
    const float4* h4 = (const float4*)g_h;   // 32 f4/row

    for (int idx = tid; idx < 128 * 64; idx += 256) {
        int k = idx >> 6, n = idx & 63;
        sWb[k * SB + n] = cvt_tf32(oW2[k * 256 + slice * 64 + n]);
    }

    const int w = tid >> 5;
    const int lane = tid & 31;
    const int g = lane >> 2;
    const int t = lane & 3;

    for (int tile = blockIdx.x; tile < NTILE_M; tile += gridDim.x) {
        const int gbase = tile * 128;

        for (int idx = tid; idx < 128 * 32; idx += 256) {
            int row = idx >> 5, c4 = idx & 31;
            int gr = gbase + row; if (gr >= MCLUS) gr = MCLUS - 1;
            cpasync16(sA + row * SA + c4 * 4, h4 + (size_t)gr * 32 + c4);
        }
        cp_commit();
        cp_wait0();
        __syncthreads();

        float acc[8][4];
#pragma unroll
        for (int nf = 0; nf < 8; nf++) {
            acc[nf][0] = 0.f; acc[nf][1] = 0.f; acc[nf][2] = 0.f; acc[nf][3] = 0.f;
        }

        const float* Ar0 = sA + (w * 16 + g) * SA;
        const float* Ar1 = Ar0 + 8 * SA;

#pragma unroll 1
        for (int kf = 0; kf < 16; kf++) {
            int k0 = kf * 8;
            unsigned a0 = cvt_tf32(Ar0[k0 + t]);
            unsigned a1 = cvt_tf32(Ar1[k0 + t]);
            unsigned a2 = cvt_tf32(Ar0[k0 + t + 4]);
            unsigned a3 = cvt_tf32(Ar1[k0 + t + 4]);
            const unsigned* B0 = sWb + (k0 + t) * SB + g;
            const unsigned* B1 = sWb + (k0 + t + 4) * SB + g;
#pragma unroll
            for (int nf = 0; nf < 8; nf++) {
                mma_tf32(acc[nf], a0, a1, a2, a3, B0[nf * 8], B1[nf * 8]);
            }
        }

        int r0 = gbase + w * 16 + g;
        int r1 = r0 + 8;
#pragma unroll
        for (int nf = 0; nf < 8; nf++) {
            int c0 = slice * 64 + nf * 8 + 2 * t;
            float bb0 = __ldg(ob2 + c0), bb1 = __ldg(ob2 + c0 + 1);
            if (r0 < MCLUS)
                *(float2*)(out + (size_t)r0 * 256 + c0) =
                    make_float2(fmaxf(acc[nf][0] + bb0, 0.f), fmaxf(acc[nf][1] + bb1, 0.f));
            if (r1 < MCLUS)
                *(float2*)(out + (size_t)r1 * 256 + c0) =
                    make_float2(fmaxf(acc[nf][2] + bb0, 0.f), fmaxf(acc[nf][3] + bb1, 0.f));
        }
        __syncthreads();
    }
}

extern "C" void kernel_launch(void* const* d_in, const int* in_sizes, int n_in,
                              void* d_out, int out_size) {
    const float* feat = (const float*)d_in[0];
    const float* pts  = (const float*)d_in[1];
    const float* ctr  = (const float*)d_in[2];
    const int*   lab  = (const int*)d_in[3];
    const float* aW1  = (const float*)d_in[4];
    const float* ab1  = (const float*)d_in[5];
    const float* aW2  = (const float*)d_in[6];
    const float* ab2  = (const float*)d_in[7];
    const float* oW1  = (const float*)d_in[8];
    const float* ob1  = (const float*)d_in[9];
    const float* oW2  = (const float*)d_in[10];
    const float* ob2  = (const float*)d_in[11];
    float* out = (float*)d_out;

    const int attSmem = 128 * SA * 4 + 136 * SB * 4 + (64 + 64 + 128) * 4 + 128 * 4 + 16;
    const int bSmem   = 128 * SA * 4 + 136 * SB * 4;
    const int cSmem   = 128 * SA * 4 + 128 * SB * 4;

    static int inited = 0;
    if (!inited) {
        cudaFuncSetAttribute(att_scatter_kernel, cudaFuncAttributeMaxDynamicSharedMemorySize, attSmem);
        cudaFuncSetAttribute(gemmB_kernel, cudaFuncAttributeMaxDynamicSharedMemorySize, bSmem);
        cudaFuncSetAttribute(gemmC_kernel, cudaFuncAttributeMaxDynamicSharedMemorySize, cSmem);
        inited = 1;
    }

    zero_agg_kernel<<<2048, 256>>>();
    att_scatter_kernel<<<296, 256, attSmem>>>(feat, pts, ctr, lab,
                                              aW1, ab1, aW2, ab2);
    gemmB_kernel<<<dim3(148, 2), 256, bSmem>>>(oW1, ob1);
    gemmC_kernel<<<dim3(74, 4), 256, cSmem>>>(oW2, ob2, out);
}

// round 12
// speedup vs baseline: 2.0276x; 1.2785x over previous
#include <cuda_runtime.h>
#include <math.h>

#define NPTS   500000
#define MCLUS  50000
#define NTILE_ATT ((NPTS + 127) / 128)    // 3907
#define NTILE_M   ((MCLUS + 127) / 128)   // 391

__device__ float g_agg[(size_t)MCLUS * 132];   // 131 used + 1 pad
__device__ float g_h[(size_t)MCLUS * 128];

// ---------------- helpers ----------------
__device__ __forceinline__ void red4(float* addr, float a, float b, float c, float d) {
    asm volatile("red.global.add.v4.f32 [%0], {%1,%2,%3,%4};"
                 :: "l"(addr), "f"(a), "f"(b), "f"(c), "f"(d) : "memory");
}
__device__ __forceinline__ void cpasync16(void* smem_dst, const void* gsrc) {
    unsigned saddr = (unsigned)__cvta_generic_to_shared(smem_dst);
    asm volatile("cp.async.cg.shared.global [%0], [%1], 16;" :: "r"(saddr), "l"(gsrc));
}
__device__ __forceinline__ void cp_commit() { asm volatile("cp.async.commit_group;"); }
__device__ __forceinline__ void cp_wait0()  { asm volatile("cp.async.wait_group 0;" ::: "memory"); }

__device__ __forceinline__ unsigned cvt_tf32(float f) {
    unsigned x;
    asm("cvt.rna.tf32.f32 %0, %1;" : "=r"(x) : "f"(f));
    return x;
}
__device__ __forceinline__ void mma_tf32(float* c, unsigned a0, unsigned a1,
                                         unsigned a2, unsigned a3,
                                         unsigned b0, unsigned b1) {
    asm volatile(
        "mma.sync.aligned.m16n8k8.row.col.f32.tf32.tf32.f32 "
        "{%0,%1,%2,%3}, {%4,%5,%6,%7}, {%8,%9}, {%0,%1,%2,%3};"
        : "+f"(c[0]), "+f"(c[1]), "+f"(c[2]), "+f"(c[3])
        : "r"(a0), "r"(a1), "r"(a2), "r"(a3), "r"(b0), "r"(b1));
}

#define SA 136   // A-tile row stride (floats): conflict-free
#define SB 72    // B-tile row stride (tf32 words): conflict-free

// ---------------- kernel 0: zero agg ----------------
__global__ void zero_agg_kernel() {
    const size_t total4 = (size_t)MCLUS * 132 / 4;
    float4* p = (float4*)g_agg;
    float4 z = make_float4(0.f, 0.f, 0.f, 0.f);
    for (size_t i = blockIdx.x * blockDim.x + threadIdx.x; i < total4;
         i += (size_t)gridDim.x * blockDim.x)
        p[i] = z;
}

// ============ kernel 1: attention MLP (tf32 MMA) + scatter ============
// Persistent, per-warp independent pipelines: warp w owns tile rows w*16..w*16+15.
__global__ void __launch_bounds__(256, 2) att_scatter_kernel(
    const float* __restrict__ feat, const float* __restrict__ pts,
    const float* __restrict__ ctr, const int* __restrict__ lab,
    const float* __restrict__ aW1, const float* __restrict__ ab1,
    const float* __restrict__ aW2, const float* __restrict__ ab2)
{
    extern __shared__ char dynRaw[];
    float*    sA  = (float*)dynRaw;                       // 128*SA floats
    unsigned* sWb = (unsigned*)(dynRaw + 128 * SA * 4);   // 136*SB tf32 bits
    float*    sB1 = (float*)(dynRaw + 128 * SA * 4 + 136 * SB * 4);  // 64
    float*    sA2 = sB1 + 64;          // 64
    float*    sAtt = sA2 + 64;         // 128
    int*      sLab = (int*)(sAtt + 128);  // 128
    float*    sb2p = (float*)(sLab + 128);

    const int tid = threadIdx.x;
    const float4* f4 = (const float4*)feat;

    // stage weights (tf32-rounded) + biases ONCE (only block-wide sync in kernel)
    for (int idx = tid; idx < 136 * 64; idx += 256) {
        int k = idx >> 6, n = idx & 63;
        float v = (k < 131) ? aW1[k * 64 + n] : 0.f;
        sWb[k * SB + n] = cvt_tf32(v);
    }
    if (tid < 64) { sB1[tid] = ab1[tid]; sA2[tid] = aW2[tid]; }
    if (tid == 0) *sb2p = ab2[0];
    __syncthreads();

    const int w = tid >> 5;
    const int lane = tid & 31;
    const int g = lane >> 2;
    const int t = lane & 3;
    const int rbase = w * 16;
    const float b2v = *sb2p;

    for (int tile = blockIdx.x; tile < NTILE_ATT; tile += gridDim.x) {
        const int gbase = tile * 128;

        // per-warp stage: own 16 rows of feat
        for (int idx = lane; idx < 16 * 32; idx += 32) {
            int r = idx >> 5, c4 = idx & 31;
            int gr = gbase + rbase + r; if (gr >= NPTS) gr = NPTS - 1;
            cpasync16(sA + (rbase + r) * SA + c4 * 4, f4 + (size_t)gr * 32 + c4);
        }
        cp_commit();
        if (lane < 16) {
            int rl = rbase + lane;
            int row = gbase + rl;
            int rc = (row < NPTS) ? row : (NPTS - 1);
            int l = lab[rc];
            sLab[rl] = l;
            float* Ar = sA + rl * SA;
            Ar[128] = ctr[l * 3 + 0] - pts[rc * 3 + 0];
            Ar[129] = ctr[l * 3 + 1] - pts[rc * 3 + 1];
            Ar[130] = ctr[l * 3 + 2] - pts[rc * 3 + 2];
            Ar[131] = 0.f; Ar[132] = 0.f; Ar[133] = 0.f; Ar[134] = 0.f; Ar[135] = 0.f;
        }
        cp_wait0();
        __syncwarp();

        float acc[8][4];
#pragma unroll
        for (int nf = 0; nf < 8; nf++) {
            acc[nf][0] = 0.f; acc[nf][1] = 0.f; acc[nf][2] = 0.f; acc[nf][3] = 0.f;
        }

        const float* Ar0 = sA + (rbase + g) * SA;
        const float* Ar1 = Ar0 + 8 * SA;

#pragma unroll 1
        for (int kf = 0; kf < 17; kf++) {
            int k0 = kf * 8;
            unsigned a0 = cvt_tf32(Ar0[k0 + t]);
            unsigned a1 = cvt_tf32(Ar1[k0 + t]);
            unsigned a2 = cvt_tf32(Ar0[k0 + t + 4]);
            unsigned a3 = cvt_tf32(Ar1[k0 + t + 4]);
            const unsigned* B0 = sWb + (k0 + t) * SB + g;
            const unsigned* B1 = sWb + (k0 + t + 4) * SB + g;
#pragma unroll
            for (int nf = 0; nf < 8; nf++) {
                mma_tf32(acc[nf], a0, a1, a2, a3, B0[nf * 8], B1[nf * 8]);
            }
        }

        // epilogue: bias+relu -> dot aW2 -> reduce over t -> sigmoid -> sAtt
        {
            float s0 = 0.f, s1 = 0.f;
#pragma unroll
            for (int nf = 0; nf < 8; nf++) {
                int c0 = nf * 8 + 2 * t, c1 = c0 + 1;
                float bb0 = sB1[c0], bb1 = sB1[c1];
                float w0 = sA2[c0], w1 = sA2[c1];
                s0 += fmaxf(acc[nf][0] + bb0, 0.f) * w0 + fmaxf(acc[nf][1] + bb1, 0.f) * w1;
                s1 += fmaxf(acc[nf][2] + bb0, 0.f) * w0 + fmaxf(acc[nf][3] + bb1, 0.f) * w1;
            }
            s0 += __shfl_xor_sync(0xffffffffu, s0, 1);
            s0 += __shfl_xor_sync(0xffffffffu, s0, 2);
            s1 += __shfl_xor_sync(0xffffffffu, s1, 1);
            s1 += __shfl_xor_sync(0xffffffffu, s1, 2);
            if (t == 0) {
                sAtt[rbase + g]     = 1.f / (1.f + expf(-(s0 + b2v)));
                sAtt[rbase + g + 8] = 1.f / (1.f + expf(-(s1 + b2v)));
            }
        }
        __syncwarp();

        // per-warp scatter: 16 rows x 33 red4 from the raw-fp32 A tile
        for (int idx = lane; idx < 16 * 33; idx += 32) {
            int r = idx / 33, c = idx - r * 33;
            int rl = rbase + r;
            int grow = gbase + rl;
            if (grow < NPTS) {
                float a = sAtt[rl];
                int l = sLab[rl];
                float4 v = *(const float4*)(sA + rl * SA + c * 4);
                red4(g_agg + (size_t)l * 132 + c * 4,
                     v.x * a, v.y * a, v.z * a, v.w * a);
            }
        }
        __syncwarp();   // fence: scatter LDS done before next-tile cp.async overwrite
    }
}

// ============ kernel 2: h = relu(agg @ oW1 + ob1)  (tf32 MMA) ============
// grid (148, 2): y = 64-col slice; persistent, per-warp pipelines
__global__ void __launch_bounds__(256, 2) gemmB_kernel(
    const float* __restrict__ oW1, const float* __restrict__ ob1)
{
    extern __shared__ char dynRaw[];
    float*    sA  = (float*)dynRaw;                       // 128*SA
    unsigned* sWb = (unsigned*)(dynRaw + 128 * SA * 4);   // 136*SB

    const int tid = threadIdx.x;
    const int slice = blockIdx.y;
    const float4* a4 = (const float4*)g_agg;   // 33 f4/row

    for (int idx = tid; idx < 136 * 64; idx += 256) {
        int k = idx >> 6, n = idx & 63;
        float v = (k < 131) ? oW1[k * 128 + slice * 64 + n] : 0.f;
        sWb[k * SB + n] = cvt_tf32(v);
    }
    __syncthreads();

    const int w = tid >> 5;
    const int lane = tid & 31;
    const int g = lane >> 2;
    const int t = lane & 3;
    const int rbase = w * 16;

    // hoist biases
    float bias0[8], bias1[8];
#pragma unroll
    for (int nf = 0; nf < 8; nf++) {
        int c0 = slice * 64 + nf * 8 + 2 * t;
        bias0[nf] = __ldg(ob1 + c0);
        bias1[nf] = __ldg(ob1 + c0 + 1);
    }

    for (int tile = blockIdx.x; tile < NTILE_M; tile += gridDim.x) {
        const int gbase = tile * 128;

        for (int idx = lane; idx < 16 * 33; idx += 32) {
            int r = idx / 33, c4 = idx - r * 33;
            int gr = gbase + rbase + r; if (gr >= MCLUS) gr = MCLUS - 1;
            cpasync16(sA + (rbase + r) * SA + c4 * 4, a4 + (size_t)gr * 33 + c4);
        }
        cp_commit();
        if (lane < 16) {   // zero A cols 132..135
            float* Ar = sA + (rbase + lane) * SA;
            Ar[132] = 0.f; Ar[133] = 0.f; Ar[134] = 0.f; Ar[135] = 0.f;
        }
        cp_wait0();
        __syncwarp();

        float acc[8][4];
#pragma unroll
        for (int nf = 0; nf < 8; nf++) {
            acc[nf][0] = 0.f; acc[nf][1] = 0.f; acc[nf][2] = 0.f; acc[nf][3] = 0.f;
        }

        const float* Ar0 = sA + (rbase + g) * SA;
        const float* Ar1 = Ar0 + 8 * SA;

#pragma unroll 1
        for (int kf = 0; kf < 17; kf++) {
            int k0 = kf * 8;
            unsigned a0 = cvt_tf32(Ar0[k0 + t]);
            unsigned a1 = cvt_tf32(Ar1[k0 + t]);
            unsigned a2 = cvt_tf32(Ar0[k0 + t + 4]);
            unsigned a3 = cvt_tf32(Ar1[k0 + t + 4]);
            const unsigned* B0 = sWb + (k0 + t) * SB + g;
            const unsigned* B1 = sWb + (k0 + t + 4) * SB + g;
#pragma unroll
            for (int nf = 0; nf < 8; nf++) {
                mma_tf32(acc[nf], a0, a1, a2, a3, B0[nf * 8], B1[nf * 8]);
            }
        }

        int r0 = gbase + rbase + g;
        int r1 = r0 + 8;
#pragma unroll
        for (int nf = 0; nf < 8; nf++) {
            int c0 = slice * 64 + nf * 8 + 2 * t;
            if (r0 < MCLUS)
                *(float2*)(g_h + (size_t)r0 * 128 + c0) =
                    make_float2(fmaxf(acc[nf][0] + bias0[nf], 0.f),
                                fmaxf(acc[nf][1] + bias1[nf], 0.f));
            if (r1 < MCLUS)
                *(float2*)(g_h + (size_t)r1 * 128 + c0) =
                    make_float2(fmaxf(acc[nf][2] + bias0[nf], 0.f),
                                fmaxf(acc[nf][3] + bias1[nf], 0.f));
        }
        __syncwarp();   // compute LDS done before next-tile cp.async overwrite
    }
}

// ============ kernel 3: out = relu(h @ oW2 + ob2)  (tf32 MMA) ============
// grid (74, 4): y = 64-col slice; persistent, per-warp pipelines
__global__ void __launch_bounds__(256, 2) gemmC_kernel(
    const float* __restrict__ oW2, const float* __restrict__ ob2,
    float* __restrict__ out)
{
    extern __shared__ char dynRaw[];
    float*    sA  = (float*)dynRaw;                       // 128*SA
    unsigned* sWb = (unsigned*)(dynRaw + 128 * SA * 4);   // 128*SB

    const int tid = threadIdx.x;
    const int slice = blockIdx.y;
    const float4* h4 = (const float4*)g_h;   // 32 f4/row

    for (int idx = tid; idx < 128 * 64; idx += 256) {
        int k = idx >> 6, n = idx & 63;
        sWb[k * SB + n] = cvt_tf32(oW2[k * 256 + slice * 64 + n]);
    }
    __syncthreads();

    const int w = tid >> 5;
    const int lane = tid & 31;
    const int g = lane >> 2;
    const int t = lane & 3;
    const int rbase = w * 16;

    float bias0[8], bias1[8];
#pragma unroll
    for (int nf = 0; nf < 8; nf++) {
        int c0 = slice * 64 + nf * 8 + 2 * t;
        bias0[nf] = __ldg(ob2 + c0);
        bias1[nf] = __ldg(ob2 + c0 + 1);
    }

    for (int tile = blockIdx.x; tile < NTILE_M; tile += gridDim.x) {
        const int gbase = tile * 128;

        for (int idx = lane; idx < 16 * 32; idx += 32) {
            int r = idx >> 5, c4 = idx & 31;
            int gr = gbase + rbase + r; if (gr >= MCLUS) gr = MCLUS - 1;
            cpasync16(sA + (rbase + r) * SA + c4 * 4, h4 + (size_t)gr * 32 + c4);
        }
        cp_commit();
        cp_wait0();
        __syncwarp();

        float acc[8][4];
#pragma unroll
        for (int nf = 0; nf < 8; nf++) {
            acc[nf][0] = 0.f; acc[nf][1] = 0.f; acc[nf][2] = 0.f; acc[nf][3] = 0.f;
        }

        const float* Ar0 = sA + (rbase + g) * SA;
        const float* Ar1 = Ar0 + 8 * SA;

#pragma unroll 1
        for (int kf = 0; kf < 16; kf++) {
            int k0 = kf * 8;
            unsigned a0 = cvt_tf32(Ar0[k0 + t]);
            unsigned a1 = cvt_tf32(Ar1[k0 + t]);
            unsigned a2 = cvt_tf32(Ar0[k0 + t + 4]);
            unsigned a3 = cvt_tf32(Ar1[k0 + t + 4]);
            const unsigned* B0 = sWb + (k0 + t) * SB + g;
            const unsigned* B1 = sWb + (k0 + t + 4) * SB + g;
#pragma unroll
            for (int nf = 0; nf < 8; nf++) {
                mma_tf32(acc[nf], a0, a1, a2, a3, B0[nf * 8], B1[nf * 8]);
            }
        }

        int r0 = gbase + rbase + g;
        int r1 = r0 + 8;
#pragma unroll
        for (int nf = 0; nf < 8; nf++) {
            int c0 = slice * 64 + nf * 8 + 2 * t;
            if (r0 < MCLUS)
                *(float2*)(out + (size_t)r0 * 256 + c0) =
                    make_float2(fmaxf(acc[nf][0] + bias0[nf], 0.f),
                                fmaxf(acc[nf][1] + bias1[nf], 0.f));
            if (r1 < MCLUS)
                *(float2*)(out + (size_t)r1 * 256 + c0) =
                    make_float2(fmaxf(acc[nf][2] + bias0[nf], 0.f),
                                fmaxf(acc[nf][3] + bias1[nf], 0.f));
        }
        __syncwarp();
    }
}

extern "C" void kernel_launch(void* const* d_in, const int* in_sizes, int n_in,
                              void* d_out, int out_size) {
    const float* feat = (const float*)d_in[0];
    const float* pts  = (const float*)d_in[1];
    const float* ctr  = (const float*)d_in[2];
    const int*   lab  = (const int*)d_in[3];
    const float* aW1  = (const float*)d_in[4];
    const float* ab1  = (const float*)d_in[5];
    const float* aW2  = (const float*)d_in[6];
    const float* ab2  = (const float*)d_in[7];
    const float* oW1  = (const float*)d_in[8];
    const float* ob1  = (const float*)d_in[9];
    const float* oW2  = (const float*)d_in[10];
    const float* ob2  = (const float*)d_in[11];
    float* out = (float*)d_out;

    const int attSmem = 128 * SA * 4 + 136 * SB * 4 + (64 + 64 + 128) * 4 + 128 * 4 + 16;
    const int bSmem   = 128 * SA * 4 + 136 * SB * 4;
    const int cSmem   = 128 * SA * 4 + 128 * SB * 4;

    static int inited = 0;
    if (!inited) {
        cudaFuncSetAttribute(att_scatter_kernel, cudaFuncAttributeMaxDynamicSharedMemorySize, attSmem);
        cudaFuncSetAttribute(gemmB_kernel, cudaFuncAttributeMaxDynamicSharedMemorySize, bSmem);
        cudaFuncSetAttribute(gemmC_kernel, cudaFuncAttributeMaxDynamicSharedMemorySize, cSmem);
        inited = 1;
    }

    zero_agg_kernel<<<2048, 256>>>();
    att_scatter_kernel<<<296, 256, attSmem>>>(feat, pts, ctr, lab,
                                              aW1, ab1, aW2, ab2);
    gemmB_kernel<<<dim3(148, 2), 256, bSmem>>>(oW1, ob1);
    gemmC_kernel<<<dim3(74, 4), 256, cSmem>>>(oW2, ob2, out);
}